// round 1
// baseline (speedup 1.0000x reference)
#include <cuda_runtime.h>

#define BN   4
#define NF   8
#define CC   8
#define NPIX (512 * 512)

// Scratch (no allocs allowed): 256 + 32 + 4 floats
__device__ float g_sums[BN][CC][NF];
__device__ float g_counts[BN][CC];
__device__ float g_dist[BN];

__global__ void k_init() {
    int t = threadIdx.x;
    if (t < BN * CC * NF) ((float*)g_sums)[t]   = 0.f;
    if (t < BN * CC)      ((float*)g_counts)[t] = 0.f;
    if (t < BN)           g_dist[t]             = 0.f;
}

// Pass 1: per-cluster counts + feature sums. Register accumulators (predicated
// one-hot FFMA) -> warp shuffle -> shared -> global atomics.
__global__ void __launch_bounds__(256) k_pass1(const float* __restrict__ pred,
                                               const int* __restrict__ tgt) {
    const int b = blockIdx.y;
    const float* p = pred + (size_t)b * NF * NPIX;
    const int*   g = tgt  + (size_t)b * NPIX;

    float acc[CC][NF];
    float cnt[CC];
#pragma unroll
    for (int c = 0; c < CC; c++) {
        cnt[c] = 0.f;
#pragma unroll
        for (int f = 0; f < NF; f++) acc[c][f] = 0.f;
    }

    for (int n = blockIdx.x * blockDim.x + threadIdx.x; n < NPIX;
         n += gridDim.x * blockDim.x) {
        int lab = g[n];
        float v[NF];
#pragma unroll
        for (int f = 0; f < NF; f++) v[f] = p[f * NPIX + n];
#pragma unroll
        for (int c = 0; c < CC; c++) {
            float m = (lab == c) ? 1.f : 0.f;
            cnt[c] += m;
#pragma unroll
            for (int f = 0; f < NF; f++) acc[c][f] = fmaf(m, v[f], acc[c][f]);
        }
    }

    // warp-level tree reduce of the 72 accumulators
#pragma unroll
    for (int c = 0; c < CC; c++) {
#pragma unroll
        for (int f = 0; f < NF; f++) {
            float x = acc[c][f];
#pragma unroll
            for (int o = 16; o > 0; o >>= 1) x += __shfl_down_sync(0xffffffffu, x, o);
            acc[c][f] = x;
        }
        float x = cnt[c];
#pragma unroll
        for (int o = 16; o > 0; o >>= 1) x += __shfl_down_sync(0xffffffffu, x, o);
        cnt[c] = x;
    }

    __shared__ float ss[CC * NF + CC];
    int tid = threadIdx.x;
    if (tid < CC * NF + CC) ss[tid] = 0.f;
    __syncthreads();
    if ((tid & 31) == 0) {
#pragma unroll
        for (int c = 0; c < CC; c++) {
#pragma unroll
            for (int f = 0; f < NF; f++) atomicAdd(&ss[c * NF + f], acc[c][f]);
            atomicAdd(&ss[CC * NF + c], cnt[c]);
        }
    }
    __syncthreads();
    if (tid < CC * NF)
        atomicAdd(&((float*)g_sums)[b * CC * NF + tid], ss[tid]);
    else if (tid < CC * NF + CC)
        atomicAdd(&g_counts[b][tid - CC * NF], ss[tid]);
}

// Pass 2: total hinge-squared distance to own-cluster mean.
__global__ void __launch_bounds__(256) k_pass2(const float* __restrict__ pred,
                                               const int* __restrict__ tgt) {
    const int b = blockIdx.y;
    __shared__ float smean[NF][CC];  // [f][c] -> conflict-free across labs
    int tid = threadIdx.x;
    if (tid < CC * NF) {
        int c = tid & 7, f = tid >> 3;
        smean[f][c] = g_sums[b][c][f] / g_counts[b][c];
    }
    __syncthreads();

    const float* p = pred + (size_t)b * NF * NPIX;
    const int*   g = tgt  + (size_t)b * NPIX;
    float local = 0.f;
    for (int n = blockIdx.x * blockDim.x + threadIdx.x; n < NPIX;
         n += gridDim.x * blockDim.x) {
        int lab = g[n];
        float d2 = 0.f;
#pragma unroll
        for (int f = 0; f < NF; f++) {
            float d = smean[f][lab] - p[f * NPIX + n];
            d2 = fmaf(d, d, d2);
        }
        float t = sqrtf(d2) - 0.5f;           // DELTA_V
        t = fminf(fmaxf(t, 0.f), 100000.f);
        local = fmaf(t, t, local);
    }

#pragma unroll
    for (int o = 16; o > 0; o >>= 1) local += __shfl_down_sync(0xffffffffu, local, o);
    __shared__ float sred[8];
    if ((tid & 31) == 0) sred[tid >> 5] = local;
    __syncthreads();
    if (tid == 0) {
        float s = 0.f;
#pragma unroll
        for (int w = 0; w < 8; w++) s += sred[w];
        atomicAdd(&g_dist[b], s);
    }
}

// Finalize: 256 threads = B*C*C (b, i, j) tuples. i!=j -> l_dist pair;
// i==j -> l_reg term + 1/count term for the l_var quirk.
__global__ void __launch_bounds__(256) k_final(float* __restrict__ out) {
    __shared__ float smu[BN][CC][NF];
    __shared__ float s_ldist[BN], s_lreg[BN], s_inv[BN];
    int tid = threadIdx.x;
    int b = tid >> 6, i = (tid >> 3) & 7, j = tid & 7;

    smu[b][i][j] = g_sums[b][i][j] / g_counts[b][i];  // tid covers all (b,c,f)
    if (tid < BN) { s_ldist[tid] = 0.f; s_lreg[tid] = 0.f; s_inv[tid] = 0.f; }
    __syncthreads();

    if (i != j) {
        float d2 = 0.f;
#pragma unroll
        for (int f = 0; f < NF; f++) {
            float d = smu[b][i][f] - smu[b][j][f];
            d2 = fmaf(d, d, d2);
        }
        float t = 3.0f - sqrtf(d2);           // 2 * DELTA_D
        t = fminf(fmaxf(t, 0.f), 100000.f);
        atomicAdd(&s_ldist[b], t * t);
    } else {
        float d2 = 0.f;
#pragma unroll
        for (int f = 0; f < NF; f++) d2 = fmaf(smu[b][i][f], smu[b][i][f], d2);
        atomicAdd(&s_lreg[b], sqrtf(d2));
        atomicAdd(&s_inv[b], 1.0f / g_counts[b][i]);
    }
    __syncthreads();

    if (tid == 0) {
        float total = 0.f;
#pragma unroll
        for (int bb = 0; bb < BN; bb++) {
            float l_var  = g_dist[bb] * s_inv[bb] / (float)CC;
            float l_dist = s_ldist[bb] / (float)(CC * (CC - 1));
            float l_reg  = s_lreg[bb] / (float)CC;
            total += l_var + l_dist + 0.001f * l_reg;
        }
        out[0] = total / (float)BN;
    }
}

extern "C" void kernel_launch(void* const* d_in, const int* in_sizes, int n_in,
                              void* d_out, int out_size) {
    const float* pred = (const float*)d_in[0];
    const int*   tgt  = (const int*)d_in[1];
    float*       out  = (float*)d_out;
    (void)in_sizes; (void)n_in; (void)out_size;

    k_init<<<1, 320>>>();
    dim3 grid(256, BN);
    k_pass1<<<grid, 256>>>(pred, tgt);
    k_pass2<<<grid, 256>>>(pred, tgt);
    k_final<<<1, 256>>>(out);
}

// round 2
// speedup vs baseline: 1.7074x; 1.7074x over previous
#include <cuda_runtime.h>

#define BN   4
#define NF   8
#define CC   8
#define NPIX (512 * 512)
#define NG   (NPIX / 4)

struct Scratch {
    float sums[BN][CC][NF];   // 256
    float counts[BN][CC];     // 32
    float dist[BN];           // 4
    unsigned int ticket;
};
__device__ Scratch g_s;

__device__ __forceinline__ unsigned long long ffma2(unsigned long long a,
                                                    unsigned long long b,
                                                    unsigned long long c) {
    unsigned long long d;
    asm("fma.rn.f32x2 %0, %1, %2, %3;" : "=l"(d) : "l"(a), "l"(b), "l"(c));
    return d;
}
__device__ __forceinline__ unsigned long long fadd2(unsigned long long a,
                                                    unsigned long long b) {
    unsigned long long d;
    asm("add.rn.f32x2 %0, %1, %2;" : "=l"(d) : "l"(a), "l"(b));
    return d;
}
__device__ __forceinline__ unsigned long long pack2(float lo, float hi) {
    unsigned long long r;
    asm("mov.b64 %0, {%1, %2};" : "=l"(r) : "f"(lo), "f"(hi));
    return r;
}
__device__ __forceinline__ void unpack2(unsigned long long v, float& lo, float& hi) {
    asm("mov.b64 {%0, %1}, %2;" : "=f"(lo), "=f"(hi) : "l"(v));
}
__device__ __forceinline__ float f4get(const float4 v, int i) {
    return i == 0 ? v.x : i == 1 ? v.y : i == 2 ? v.z : v.w;
}
__device__ __forceinline__ int i4get(const int4 v, int i) {
    return i == 0 ? v.x : i == 1 ? v.y : i == 2 ? v.z : v.w;
}

// ---------------------------------------------------------------------------
// Pass 1: per-cluster counts + feature sums.
// float4 loads, packed f32x2 FMA one-hot accumulate, int counts on ALU pipe.
// ---------------------------------------------------------------------------
__global__ void __launch_bounds__(128) k_pass1(const float* __restrict__ pred,
                                               const int* __restrict__ tgt) {
    const int b = blockIdx.y;
    const float4* p = (const float4*)(pred + (size_t)b * NF * NPIX);
    const int4*   g = (const int4*)(tgt + (size_t)b * NPIX);
    const unsigned long long ONE2 = 0x3F8000003F800000ull;

    unsigned long long acc[CC][4];  // [cluster][feature-pair]
    int icnt[CC];
#pragma unroll
    for (int c = 0; c < CC; c++) {
        icnt[c] = 0;
#pragma unroll
        for (int k = 0; k < 4; k++) acc[c][k] = 0ull;
    }

    for (int n = blockIdx.x * blockDim.x + threadIdx.x; n < NG;
         n += gridDim.x * blockDim.x) {
        int4 lab4 = g[n];
        float4 v[NF];
#pragma unroll
        for (int f = 0; f < NF; f++) v[f] = p[f * (NPIX / 4) + n];

#pragma unroll
        for (int px = 0; px < 4; px++) {
            int lab = i4get(lab4, px);
            unsigned long long pr[4];
#pragma unroll
            for (int k = 0; k < 4; k++)
                pr[k] = pack2(f4get(v[2 * k], px), f4get(v[2 * k + 1], px));
#pragma unroll
            for (int c = 0; c < CC; c++) {
                bool hit = (lab == c);
                unsigned long long m2 = hit ? ONE2 : 0ull;
                icnt[c] += hit;
#pragma unroll
                for (int k = 0; k < 4; k++) acc[c][k] = ffma2(m2, pr[k], acc[c][k]);
            }
        }
    }

    // warp tree-reduce (packed adds)
#pragma unroll
    for (int c = 0; c < CC; c++) {
#pragma unroll
        for (int k = 0; k < 4; k++) {
            unsigned long long x = acc[c][k];
#pragma unroll
            for (int o = 16; o > 0; o >>= 1)
                x = fadd2(x, __shfl_down_sync(0xffffffffu, x, o));
            acc[c][k] = x;
        }
        int ic = icnt[c];
#pragma unroll
        for (int o = 16; o > 0; o >>= 1) ic += __shfl_down_sync(0xffffffffu, ic, o);
        icnt[c] = ic;
    }

    __shared__ float sw[4][72];  // 4 warps x (64 sums + 8 counts)
    int tid = threadIdx.x, wid = tid >> 5, lane = tid & 31;
    if (lane == 0) {
#pragma unroll
        for (int c = 0; c < CC; c++) {
#pragma unroll
            for (int k = 0; k < 4; k++) {
                float lo, hi;
                unpack2(acc[c][k], lo, hi);
                sw[wid][c * NF + 2 * k]     = lo;
                sw[wid][c * NF + 2 * k + 1] = hi;
            }
            sw[wid][64 + c] = (float)icnt[c];
        }
    }
    __syncthreads();
    if (tid < 72) {
        float s = sw[0][tid] + sw[1][tid] + sw[2][tid] + sw[3][tid];
        if (tid < 64)
            atomicAdd(&((float*)g_s.sums)[b * 64 + tid], s);
        else
            atomicAdd(&g_s.counts[b][tid - 64], s);
    }
}

// ---------------------------------------------------------------------------
// Pass 2 + finalize (last-block ticket).
// ---------------------------------------------------------------------------
__global__ void __launch_bounds__(256) k_pass2(const float* __restrict__ pred,
                                               const int* __restrict__ tgt,
                                               float* __restrict__ out) {
    const int b = blockIdx.y;
    __shared__ float smean[NF][CC];
    int tid = threadIdx.x;
    if (tid < 64) {
        int c = tid & 7, f = tid >> 3;
        smean[f][c] = g_s.sums[b][c][f] / g_s.counts[b][c];
    }
    __syncthreads();

    const float4* p = (const float4*)(pred + (size_t)b * NF * NPIX);
    const int4*   g = (const int4*)(tgt + (size_t)b * NPIX);
    float local = 0.f;
    for (int n = blockIdx.x * blockDim.x + threadIdx.x; n < NG;
         n += gridDim.x * blockDim.x) {
        int4 lab4 = g[n];
        float4 v[NF];
#pragma unroll
        for (int f = 0; f < NF; f++) v[f] = p[f * (NPIX / 4) + n];
#pragma unroll
        for (int px = 0; px < 4; px++) {
            int lab = i4get(lab4, px);
            float d2 = 0.f;
#pragma unroll
            for (int f = 0; f < NF; f++) {
                float d = smean[f][lab] - f4get(v[f], px);
                d2 = fmaf(d, d, d2);
            }
            float t = sqrtf(d2) - 0.5f;  // DELTA_V
            t = fminf(fmaxf(t, 0.f), 100000.f);
            local = fmaf(t, t, local);
        }
    }

#pragma unroll
    for (int o = 16; o > 0; o >>= 1)
        local += __shfl_down_sync(0xffffffffu, local, o);
    __shared__ float sred[8];
    if ((tid & 31) == 0) sred[tid >> 5] = local;
    __syncthreads();
    if (tid == 0) {
        float s = 0.f;
#pragma unroll
        for (int w = 0; w < 8; w++) s += sred[w];
        atomicAdd(&g_s.dist[b], s);
    }

    // ---- last-block finalize ----
    __shared__ bool s_last;
    __threadfence();
    if (tid == 0) {
        unsigned int t = atomicAdd(&g_s.ticket, 1u);
        s_last = (t == gridDim.x * gridDim.y - 1);
    }
    __syncthreads();
    if (!s_last) return;

    __shared__ float smu[BN][CC][NF];
    __shared__ float s_ldist[BN], s_lreg[BN], s_inv[BN];
    int bb = tid >> 6, i = (tid >> 3) & 7, j = tid & 7;
    smu[bb][i][j] = g_s.sums[bb][i][j] / g_s.counts[bb][i];
    if (tid < BN) { s_ldist[tid] = 0.f; s_lreg[tid] = 0.f; s_inv[tid] = 0.f; }
    __syncthreads();

    if (i != j) {
        float d2 = 0.f;
#pragma unroll
        for (int f = 0; f < NF; f++) {
            float d = smu[bb][i][f] - smu[bb][j][f];
            d2 = fmaf(d, d, d2);
        }
        float t = 3.0f - sqrtf(d2);  // 2 * DELTA_D
        t = fminf(fmaxf(t, 0.f), 100000.f);
        atomicAdd(&s_ldist[bb], t * t);
    } else {
        float d2 = 0.f;
#pragma unroll
        for (int f = 0; f < NF; f++) d2 = fmaf(smu[bb][i][f], smu[bb][i][f], d2);
        atomicAdd(&s_lreg[bb], sqrtf(d2));
        atomicAdd(&s_inv[bb], 1.0f / g_s.counts[bb][i]);
    }
    __syncthreads();

    if (tid == 0) {
        float total = 0.f;
#pragma unroll
        for (int q = 0; q < BN; q++) {
            float dq = __ldcg(&g_s.dist[q]);  // written by other blocks; bypass L1
            float l_var  = dq * s_inv[q] / (float)CC;
            float l_dist = s_ldist[q] / (float)(CC * (CC - 1));
            float l_reg  = s_lreg[q] / (float)CC;
            total += l_var + l_dist + 0.001f * l_reg;
        }
        out[0] = total / (float)BN;
    }
}

extern "C" void kernel_launch(void* const* d_in, const int* in_sizes, int n_in,
                              void* d_out, int out_size) {
    const float* pred = (const float*)d_in[0];
    const int*   tgt  = (const int*)d_in[1];
    float*       out  = (float*)d_out;
    (void)in_sizes; (void)n_in; (void)out_size;

    void* scratch_ptr = nullptr;
    cudaGetSymbolAddress(&scratch_ptr, g_s);
    cudaMemsetAsync(scratch_ptr, 0, sizeof(Scratch));

    dim3 grid1(148, BN);
    k_pass1<<<grid1, 128>>>(pred, tgt);
    dim3 grid2(148, BN);
    k_pass2<<<grid2, 256>>>(pred, tgt, out);
}